// round 15
// baseline (speedup 1.0000x reference)
#include <cuda_runtime.h>

#define B 32
#define S 4096
#define DIN 1024
#define DOUT 256
#define NSEG 64
#define TILE_S 128    // rows of S per block in the segment-reduce kernel
#define TILE_M 16     // segment rows per block in the GEMM kernel

// 8 MB scratch: per-(batch,segment) sums over D_IN.
// Zero-initialized at module load; gemm_lsm_kernel re-zeroes it every call.
__device__ float g_segsum[(size_t)B * NSEG * DIN];
// 2 MB: W with every element duplicated as packed f32x2 (u64), k-major.
__device__ unsigned long long g_W2[(size_t)DIN * DOUT];

// ---------------------------------------------------------------------------
// Kernel 0: build g_W2 = dup(W) as u64 pairs. 65536 float4 -> 131072 ulonglong2.
// ---------------------------------------------------------------------------
__global__ void __launch_bounds__(256) w2_kernel(const float* __restrict__ Wm) {
    const int idx = blockIdx.x * 256 + threadIdx.x;       // float4 index
    float4 w = reinterpret_cast<const float4*>(Wm)[idx];
    unsigned long long dx, dy, dz, dw;
    asm("mov.b64 %0, {%1,%1};" : "=l"(dx) : "f"(w.x));
    asm("mov.b64 %0, {%1,%1};" : "=l"(dy) : "f"(w.y));
    asm("mov.b64 %0, {%1,%1};" : "=l"(dz) : "f"(w.z));
    asm("mov.b64 %0, {%1,%1};" : "=l"(dw) : "f"(w.w));
    ulonglong2* dst = reinterpret_cast<ulonglong2*>(g_W2) + (size_t)idx * 2;
    dst[0] = make_ulonglong2(dx, dy);
    dst[1] = make_ulonglong2(dz, dw);
}

// ---------------------------------------------------------------------------
// Kernel 1: segment-reduce enc_output over S — balanced uniform tiles.
// (R9 body, unchanged: measured ~86% of DRAM spec, at the wall)
// ---------------------------------------------------------------------------
__global__ void __launch_bounds__(256, 7) seg_tile_kernel(
    const float* __restrict__ enc,
    const int*   __restrict__ cls_pos,
    const int*   __restrict__ last_sep)
{
    const int b    = blockIdx.y;
    const int tile = blockIdx.x;
    const int tid  = threadIdx.x;

    __shared__ int sstart[NSEG];
    if (tid < NSEG) sstart[tid] = cls_pos[b * NSEG + tid];
    __syncthreads();

    const int e_sep    = last_sep[b] + 1;
    const int end_last = (e_sep > sstart[NSEG - 1]) ? e_sep : S;  // torch rule

    const int s0 = tile * TILE_S;
    const int s1 = s0 + TILE_S;

    int seg = -1;
    while (seg < NSEG - 1 && sstart[seg + 1] <= s0) seg++;
    int nxt = (seg < NSEG - 1) ? sstart[seg + 1] : 0x7fffffff;

    const float4* __restrict__ p = reinterpret_cast<const float4*>(enc)
                                 + (size_t)b * S * (DIN / 4) + tid;

    float4 acc = make_float4(0.f, 0.f, 0.f, 0.f);
    int acc_seg = seg;

#define FLUSH_ACC()                                                           \
    do { if (acc_seg >= 0) {                                                  \
        float* d_ = g_segsum + (size_t)(b * NSEG + acc_seg) * DIN + tid * 4;  \
        atomicAdd(d_ + 0, acc.x); atomicAdd(d_ + 1, acc.y);                   \
        atomicAdd(d_ + 2, acc.z); atomicAdd(d_ + 3, acc.w);                   \
    } } while (0)

    for (int base = s0; base < s1; base += 4) {
        float4 v0 = __ldcs(&p[(size_t)(base + 0) * (DIN / 4)]);
        float4 v1 = __ldcs(&p[(size_t)(base + 1) * (DIN / 4)]);
        float4 v2 = __ldcs(&p[(size_t)(base + 2) * (DIN / 4)]);
        float4 v3 = __ldcs(&p[(size_t)(base + 3) * (DIN / 4)]);

        if (seg >= 0 && base + 3 < nxt &&
            (seg < NSEG - 1 || base + 3 < end_last)) {
            acc.x += (v0.x + v1.x) + (v2.x + v3.x);
            acc.y += (v0.y + v1.y) + (v2.y + v3.y);
            acc.z += (v0.z + v1.z) + (v2.z + v3.z);
            acc.w += (v0.w + v1.w) + (v2.w + v3.w);
        } else {
            float4 v[4] = {v0, v1, v2, v3};
#pragma unroll
            for (int j = 0; j < 4; ++j) {
                const int r = base + j;
                if (r >= nxt) {
                    while (seg < NSEG - 1 && r >= sstart[seg + 1]) seg++;
                    nxt = (seg < NSEG - 1) ? sstart[seg + 1] : 0x7fffffff;
                    FLUSH_ACC();
                    acc = make_float4(0.f, 0.f, 0.f, 0.f);
                    acc_seg = seg;
                }
                const bool ok = (seg >= 0) && (seg < NSEG - 1 || r < end_last);
                if (ok) {
                    acc.x += v[j].x; acc.y += v[j].y;
                    acc.z += v[j].z; acc.w += v[j].w;
                }
            }
        }
    }
    FLUSH_ACC();
#undef FLUSH_ACC
}

// ---------------------------------------------------------------------------
// Kernel 2: R14 gemm+lsm, W chain de-fanged: loads pre-duplicated W2 (u64
// pairs) so the mainloop has NO pack movs — per k: 2 LDS.128 + 2 LDG.128 +
// 16 fma.rn.f32x2. PDL prologue prefetches this block's W2 slice to L2.
// ---------------------------------------------------------------------------
__global__ void __launch_bounds__(512, 1) gemm_lsm_kernel(
    const float* __restrict__ bias,
    const int*   __restrict__ cls_pos,
    const int*   __restrict__ last_sep,
    float*       __restrict__ out)
{
    extern __shared__ float sm[];              // 1024*20 floats = 80KB
    __shared__ float sBias[DOUT];

    const int tid = threadIdx.x;
    const int q   = tid >> 7;                  // k-quarter 0..3 (256 k each)
    const int rh  = (tid >> 6) & 1;            // row half 0..1  (8 rows each)
    const int cq  = tid & 63;                  // col quad 0..63 (4 cols each)
    const int m0  = blockIdx.x * TILE_M;

    // ---- PDL prologue: warm L2 with this block's W2 slice (16KB; 128 blocks
    // cover all 2MB). W2 was written before seg -> safe to touch pre-sync.
    if (tid < 128) {
        const char* wp = reinterpret_cast<const char*>(
            g_W2 + (size_t)blockIdx.x * 8 * DOUT) + tid * 128;
        asm volatile("prefetch.global.L2 [%0];" :: "l"(wp));
    }

#if defined(__CUDA_ARCH__) && (__CUDA_ARCH__ >= 900)
    cudaGridDependencySynchronize();           // wait for seg_tile_kernel
#endif

    if (tid < DOUT) sBias[tid] = bias[tid];

    // ---- stage A transposed: sm[k*20 + i] (one shot, one sync)
    {
        const int i  = tid >> 5;               // row 0..15
        const int kl = tid & 31;               // k lane
        const float* src = g_segsum + (size_t)(m0 + i) * DIN + kl;
#pragma unroll
        for (int j = 0; j < 32; ++j)
            sm[(kl + 32 * j) * 20 + i] = src[32 * j];
    }
    __syncthreads();

    // ---- restore g_segsum rows to zero for the next call (fire-and-forget)
    {
        float4* z = reinterpret_cast<float4*>(g_segsum + (size_t)m0 * DIN);
        const float4 z4 = make_float4(0.f, 0.f, 0.f, 0.f);
#pragma unroll
        for (int r = 0; r < 8; ++r) z[r * 512 + tid] = z4;
    }

    // ---- mainloop: acc2[rp*4+c] = packed rows {2rp, 2rp+1} of column 4cq+c
    unsigned long long acc2[16];
#pragma unroll
    for (int x = 0; x < 16; ++x) acc2[x] = 0ull;

    // W2: u64 per (k, col); per k-row 256 u64 = 128 ulonglong2.
    const ulonglong2* Wp2 = reinterpret_cast<const ulonglong2*>(g_W2)
                          + (size_t)(q * 256) * (DOUT / 2) + cq * 2;
    const float* aBase = sm + (size_t)(q * 256) * 20 + rh * 8;

    for (int kk = 0; kk < 256; kk += 4) {
        ulonglong2 w0[4], w1[4];               // cols {0,1} and {2,3}, dup'd
#pragma unroll
        for (int j = 0; j < 4; ++j) {
            w0[j] = Wp2[(size_t)(kk + j) * (DOUT / 2)];
            w1[j] = Wp2[(size_t)(kk + j) * (DOUT / 2) + 1];
        }
#pragma unroll
        for (int j = 0; j < 4; ++j) {
            const ulonglong2* ap =
                reinterpret_cast<const ulonglong2*>(aBase + (kk + j) * 20);
            ulonglong2 a01 = ap[0];   // row-pairs 0,1 (rows rbase+0..3)
            ulonglong2 a23 = ap[1];   // row-pairs 2,3 (rows rbase+4..7)
#define FMA2(idx, apair, wpair) \
            asm("fma.rn.f32x2 %0, %1, %2, %3;" : "=l"(acc2[idx]) : "l"(apair), "l"(wpair), "l"(acc2[idx]))
            FMA2(0,  a01.x, w0[j].x); FMA2(1,  a01.x, w0[j].y);
            FMA2(2,  a01.x, w1[j].x); FMA2(3,  a01.x, w1[j].y);
            FMA2(4,  a01.y, w0[j].x); FMA2(5,  a01.y, w0[j].y);
            FMA2(6,  a01.y, w1[j].x); FMA2(7,  a01.y, w1[j].y);
            FMA2(8,  a23.x, w0[j].x); FMA2(9,  a23.x, w0[j].y);
            FMA2(10, a23.x, w1[j].x); FMA2(11, a23.x, w1[j].y);
            FMA2(12, a23.y, w0[j].x); FMA2(13, a23.y, w0[j].y);
            FMA2(14, a23.y, w1[j].x); FMA2(15, a23.y, w1[j].y);
#undef FMA2
        }
    }

    // unpack: accf[r][c], r = row within half (0..7), c = col within quad
    float accf[8][4];
#pragma unroll
    for (int rp = 0; rp < 4; ++rp)
#pragma unroll
        for (int c = 0; c < 4; ++c) {
            float lo, hi;
            asm("mov.b64 {%0,%1}, %2;" : "=f"(lo), "=f"(hi) : "l"(acc2[rp * 4 + c]));
            accf[2 * rp][c]     = lo;
            accf[2 * rp + 1][c] = hi;
        }

    // ---- combine: barrier FIRST (A tile must be dead in ALL warps before
    // any buffer write), quarter q writes buf q, barrier, epilogue sums 4.
    __syncthreads();
    {
        const int rbase = rh * 8;
        float4* d_ = reinterpret_cast<float4*>(sm + q * 4096 + cq * 4);
#pragma unroll
        for (int r = 0; r < 8; ++r)
            d_[(rbase + r) * (DOUT / 4)] =
                make_float4(accf[r][0], accf[r][1], accf[r][2], accf[r][3]);
    }
    __syncthreads();

    // ---- barrier-free epilogue: warp w (0..15) owns row w; sums 4 buffers
    const int wid  = tid >> 5;
    const int lane = tid & 31;
    {
        const int g  = m0 + wid;
        const int bb = g >> 6;
        const int nn = g & (NSEG - 1);
        const int start = cls_pos[bb * NSEG + nn];
        int end;
        if (nn < NSEG - 1) end = cls_pos[bb * NSEG + nn + 1];
        else { int e2 = last_sep[bb] + 1; end = (e2 > start) ? e2 : S; }
        const float cnt = (float)(end - start);

        const float* z0 = sm + 0 * 4096 + wid * DOUT;
        const float* z1 = sm + 1 * 4096 + wid * DOUT;
        const float* z2 = sm + 2 * 4096 + wid * DOUT;
        const float* z3 = sm + 3 * 4096 + wid * DOUT;

        float z[8];
        float m = __int_as_float(0xff800000);  // -inf
#pragma unroll
        for (int j = 0; j < 8; ++j) {
            const int cc = lane + 32 * j;
            const float s01 = z0[cc] + z1[cc];
            const float s23 = z2[cc] + z3[cc];
            z[j] = fmaf(cnt, sBias[cc], s01 + s23);
            m = fmaxf(m, z[j]);
        }
#pragma unroll
        for (int off = 16; off > 0; off >>= 1)
            m = fmaxf(m, __shfl_xor_sync(0xffffffffu, m, off));

        float ssum = 0.f;
#pragma unroll
        for (int j = 0; j < 8; ++j) ssum += expf(z[j] - m);
#pragma unroll
        for (int off = 16; off > 0; off >>= 1)
            ssum += __shfl_xor_sync(0xffffffffu, ssum, off);

        const float lse = m + logf(ssum);
        float* op = out + (size_t)g * DOUT;
#pragma unroll
        for (int j = 0; j < 8; ++j)
            op[lane + 32 * j] = z[j] - lse;
    }
}

// ---------------------------------------------------------------------------
extern "C" void kernel_launch(void* const* d_in, const int* in_sizes, int n_in,
                              void* d_out, int out_size)
{
    const float* enc  = nullptr;
    const float* Wm   = nullptr;
    const float* bias = nullptr;
    const int*   cls  = nullptr;
    const int*   ls   = nullptr;
    for (int i = 0; i < n_in; ++i) {
        switch (in_sizes[i]) {
            case 134217728: enc  = (const float*)d_in[i]; break;
            case 262144:    Wm   = (const float*)d_in[i]; break;
            case 256:       bias = (const float*)d_in[i]; break;
            case 2048:      cls  = (const int*)d_in[i];   break;
            case 32:        ls   = (const int*)d_in[i];   break;
            default: break;
        }
    }

    // 0) build duplicated-W2 (65536 float4 / 256 per block)
    w2_kernel<<<256, 256>>>(Wm);

    // 1) balanced segment reduce into (pre-zeroed) g_segsum: single wave
    dim3 g1(S / TILE_S, B);
    seg_tile_kernel<<<g1, 256>>>(enc, cls, ls);

    // 2) GEMM + bias*count + log_softmax with PDL: blocks prefetch W2 to L2
    //    while seg drains, then grid-dependency-sync.
    const int smem_bytes = 1024 * 20 * (int)sizeof(float);   // 81920
    cudaFuncSetAttribute(gemm_lsm_kernel,
                         cudaFuncAttributeMaxDynamicSharedMemorySize, smem_bytes);

    cudaLaunchConfig_t cfg = {};
    cfg.gridDim          = dim3((B * NSEG) / TILE_M, 1, 1);
    cfg.blockDim         = dim3(512, 1, 1);
    cfg.dynamicSmemBytes = smem_bytes;
    cfg.stream           = 0;
    cudaLaunchAttribute attrs[1];
    attrs[0].id = cudaLaunchAttributeProgrammaticStreamSerialization;
    attrs[0].val.programmaticStreamSerializationAllowed = 1;
    cfg.attrs    = attrs;
    cfg.numAttrs = 1;

    cudaError_t err = cudaLaunchKernelEx(&cfg, gemm_lsm_kernel,
                                         bias, cls, ls, (float*)d_out);
    if (err != cudaSuccess) {
        gemm_lsm_kernel<<<(B * NSEG) / TILE_M, 512, smem_bytes>>>(
            bias, cls, ls, (float*)d_out);
    }
}

// round 16
// speedup vs baseline: 1.2073x; 1.2073x over previous
#include <cuda_runtime.h>

#define B 32
#define S 4096
#define DIN 1024
#define DOUT 256
#define NSEG 64
#define TILE_S 128    // rows of S per block in the segment-reduce kernel
#define TILE_M 16     // segment rows per block in the GEMM kernel

// 8 MB scratch: per-(batch,segment) sums over D_IN.
// Zero-initialized at module load; gemm_lsm_kernel re-zeroes it every call.
__device__ float g_segsum[(size_t)B * NSEG * DIN];

// ---------------------------------------------------------------------------
// Kernel 1: segment-reduce enc_output over S — balanced uniform tiles.
// Grid (32 tiles, 32 batches) = 1024 blocks, single wave. Measured ~6.9 TB/s
// (~87% of HBM spec) — at the wall. Loads are always 4-row batched; segment
// bookkeeping happens on registers after the loads; uniform across the block.
// ---------------------------------------------------------------------------
__global__ void __launch_bounds__(256, 7) seg_tile_kernel(
    const float* __restrict__ enc,
    const int*   __restrict__ cls_pos,
    const int*   __restrict__ last_sep)
{
    const int b    = blockIdx.y;
    const int tile = blockIdx.x;
    const int tid  = threadIdx.x;

    __shared__ int sstart[NSEG];
    if (tid < NSEG) sstart[tid] = cls_pos[b * NSEG + tid];
    __syncthreads();

    const int e_sep    = last_sep[b] + 1;
    const int end_last = (e_sep > sstart[NSEG - 1]) ? e_sep : S;  // torch rule

    const int s0 = tile * TILE_S;
    const int s1 = s0 + TILE_S;

    int seg = -1;
    while (seg < NSEG - 1 && sstart[seg + 1] <= s0) seg++;
    int nxt = (seg < NSEG - 1) ? sstart[seg + 1] : 0x7fffffff;

    const float4* __restrict__ p = reinterpret_cast<const float4*>(enc)
                                 + (size_t)b * S * (DIN / 4) + tid;

    float4 acc = make_float4(0.f, 0.f, 0.f, 0.f);
    int acc_seg = seg;

#define FLUSH_ACC()                                                           \
    do { if (acc_seg >= 0) {                                                  \
        float* d_ = g_segsum + (size_t)(b * NSEG + acc_seg) * DIN + tid * 4;  \
        atomicAdd(d_ + 0, acc.x); atomicAdd(d_ + 1, acc.y);                   \
        atomicAdd(d_ + 2, acc.z); atomicAdd(d_ + 3, acc.w);                   \
    } } while (0)

    for (int base = s0; base < s1; base += 4) {
        float4 v0 = __ldcs(&p[(size_t)(base + 0) * (DIN / 4)]);
        float4 v1 = __ldcs(&p[(size_t)(base + 1) * (DIN / 4)]);
        float4 v2 = __ldcs(&p[(size_t)(base + 2) * (DIN / 4)]);
        float4 v3 = __ldcs(&p[(size_t)(base + 3) * (DIN / 4)]);

        if (seg >= 0 && base + 3 < nxt &&
            (seg < NSEG - 1 || base + 3 < end_last)) {
            acc.x += (v0.x + v1.x) + (v2.x + v3.x);
            acc.y += (v0.y + v1.y) + (v2.y + v3.y);
            acc.z += (v0.z + v1.z) + (v2.z + v3.z);
            acc.w += (v0.w + v1.w) + (v2.w + v3.w);
        } else {
            float4 v[4] = {v0, v1, v2, v3};
#pragma unroll
            for (int j = 0; j < 4; ++j) {
                const int r = base + j;
                if (r >= nxt) {
                    while (seg < NSEG - 1 && r >= sstart[seg + 1]) seg++;
                    nxt = (seg < NSEG - 1) ? sstart[seg + 1] : 0x7fffffff;
                    FLUSH_ACC();
                    acc = make_float4(0.f, 0.f, 0.f, 0.f);
                    acc_seg = seg;
                }
                const bool ok = (seg >= 0) && (seg < NSEG - 1 || r < end_last);
                if (ok) {
                    acc.x += v[j].x; acc.y += v[j].y;
                    acc.z += v[j].z; acc.w += v[j].w;
                }
            }
        }
    }
    FLUSH_ACC();
#undef FLUSH_ACC
}

// ---------------------------------------------------------------------------
// Kernel 2: [2048,1024] @ [1024,256] + count*bias, fused log_softmax over 256.
// 512 threads: thread = (k-quarter q, row-half rh, col-quad cq), owns 8r x 4c.
// Measured optimum of the SIMT design space (rounds 4-15): per k, 2 LDS.128
// (broadcast) + 4 pack movs + 16 packed fma.rn.f32x2 + 1 LDG.128 (W) — LDS
// crossbar and fma pipe co-bound. A tile staged once into 80KB dynamic smem;
// 2-sync 4-buffer combine; barrier-free per-warp softmax epilogue; re-zeroes
// its own g_segsum rows for the next call.
// ---------------------------------------------------------------------------
__global__ void __launch_bounds__(512, 1) gemm_lsm_kernel(
    const float* __restrict__ Wm,
    const float* __restrict__ bias,
    const int*   __restrict__ cls_pos,
    const int*   __restrict__ last_sep,
    float*       __restrict__ out)
{
    extern __shared__ float sm[];              // 1024*20 floats = 80KB
    __shared__ float sBias[DOUT];

    const int tid = threadIdx.x;
    const int q   = tid >> 7;                  // k-quarter 0..3 (256 k each)
    const int rh  = (tid >> 6) & 1;            // row half 0..1  (8 rows each)
    const int cq  = tid & 63;                  // col quad 0..63 (4 cols each)
    const int m0  = blockIdx.x * TILE_M;

    if (tid < DOUT) sBias[tid] = bias[tid];

    // ---- stage A transposed: sm[k*20 + i] (one shot, one sync)
    {
        const int i  = tid >> 5;               // row 0..15
        const int kl = tid & 31;               // k lane
        const float* src = g_segsum + (size_t)(m0 + i) * DIN + kl;
#pragma unroll
        for (int j = 0; j < 32; ++j)
            sm[(kl + 32 * j) * 20 + i] = src[32 * j];
    }
    __syncthreads();

    // ---- restore g_segsum rows to zero for the next call (fire-and-forget)
    {
        float4* z = reinterpret_cast<float4*>(g_segsum + (size_t)m0 * DIN);
        const float4 z4 = make_float4(0.f, 0.f, 0.f, 0.f);
#pragma unroll
        for (int r = 0; r < 8; ++r) z[r * 512 + tid] = z4;
    }

    // ---- mainloop: acc2[rp*4+c] = packed rows {2rp, 2rp+1} of column 4cq+c
    unsigned long long acc2[16];
#pragma unroll
    for (int x = 0; x < 16; ++x) acc2[x] = 0ull;

    const float4* Wp = reinterpret_cast<const float4*>(Wm)
                     + (size_t)(q * 256) * (DOUT / 4) + cq;
    const float* aBase = sm + (size_t)(q * 256) * 20 + rh * 8;

    for (int kk = 0; kk < 256; kk += 4) {
        float4 w[4];
#pragma unroll
        for (int j = 0; j < 4; ++j) w[j] = Wp[(size_t)(kk + j) * (DOUT / 4)];
#pragma unroll
        for (int j = 0; j < 4; ++j) {
            const ulonglong2* ap =
                reinterpret_cast<const ulonglong2*>(aBase + (kk + j) * 20);
            ulonglong2 a01 = ap[0];   // row-pairs 0,1 (rows rbase+0..3)
            ulonglong2 a23 = ap[1];   // row-pairs 2,3 (rows rbase+4..7)
            unsigned long long wp0, wp1, wp2, wp3;
            asm("mov.b64 %0, {%1,%1};" : "=l"(wp0) : "f"(w[j].x));
            asm("mov.b64 %0, {%1,%1};" : "=l"(wp1) : "f"(w[j].y));
            asm("mov.b64 %0, {%1,%1};" : "=l"(wp2) : "f"(w[j].z));
            asm("mov.b64 %0, {%1,%1};" : "=l"(wp3) : "f"(w[j].w));
#define FMA2(idx, apair, wpair) \
            asm("fma.rn.f32x2 %0, %1, %2, %3;" : "=l"(acc2[idx]) : "l"(apair), "l"(wpair), "l"(acc2[idx]))
            FMA2(0,  a01.x, wp0); FMA2(1,  a01.x, wp1); FMA2(2,  a01.x, wp2); FMA2(3,  a01.x, wp3);
            FMA2(4,  a01.y, wp0); FMA2(5,  a01.y, wp1); FMA2(6,  a01.y, wp2); FMA2(7,  a01.y, wp3);
            FMA2(8,  a23.x, wp0); FMA2(9,  a23.x, wp1); FMA2(10, a23.x, wp2); FMA2(11, a23.x, wp3);
            FMA2(12, a23.y, wp0); FMA2(13, a23.y, wp1); FMA2(14, a23.y, wp2); FMA2(15, a23.y, wp3);
#undef FMA2
        }
    }

    // unpack: accf[r][c], r = row within half (0..7), c = col within quad
    float accf[8][4];
#pragma unroll
    for (int rp = 0; rp < 4; ++rp)
#pragma unroll
        for (int c = 0; c < 4; ++c) {
            float lo, hi;
            asm("mov.b64 {%0,%1}, %2;" : "=f"(lo), "=f"(hi) : "l"(acc2[rp * 4 + c]));
            accf[2 * rp][c]     = lo;
            accf[2 * rp + 1][c] = hi;
        }

    // ---- combine: barrier FIRST (A tile must be dead in ALL warps before
    // any buffer write), quarter q writes buf q, barrier, epilogue sums 4.
    __syncthreads();
    {
        const int rbase = rh * 8;
        float4* d_ = reinterpret_cast<float4*>(sm + q * 4096 + cq * 4);
#pragma unroll
        for (int r = 0; r < 8; ++r)
            d_[(rbase + r) * (DOUT / 4)] =
                make_float4(accf[r][0], accf[r][1], accf[r][2], accf[r][3]);
    }
    __syncthreads();

    // ---- barrier-free epilogue: warp w (0..15) owns row w; sums 4 buffers
    const int wid  = tid >> 5;
    const int lane = tid & 31;
    {
        const int g  = m0 + wid;
        const int bb = g >> 6;
        const int nn = g & (NSEG - 1);
        const int start = cls_pos[bb * NSEG + nn];
        int end;
        if (nn < NSEG - 1) end = cls_pos[bb * NSEG + nn + 1];
        else { int e2 = last_sep[bb] + 1; end = (e2 > start) ? e2 : S; }
        const float cnt = (float)(end - start);

        const float* z0 = sm + 0 * 4096 + wid * DOUT;
        const float* z1 = sm + 1 * 4096 + wid * DOUT;
        const float* z2 = sm + 2 * 4096 + wid * DOUT;
        const float* z3 = sm + 3 * 4096 + wid * DOUT;

        float z[8];
        float m = __int_as_float(0xff800000);  // -inf
#pragma unroll
        for (int j = 0; j < 8; ++j) {
            const int cc = lane + 32 * j;
            const float s01 = z0[cc] + z1[cc];
            const float s23 = z2[cc] + z3[cc];
            z[j] = fmaf(cnt, sBias[cc], s01 + s23);
            m = fmaxf(m, z[j]);
        }
#pragma unroll
        for (int off = 16; off > 0; off >>= 1)
            m = fmaxf(m, __shfl_xor_sync(0xffffffffu, m, off));

        float ssum = 0.f;
#pragma unroll
        for (int j = 0; j < 8; ++j) ssum += expf(z[j] - m);
#pragma unroll
        for (int off = 16; off > 0; off >>= 1)
            ssum += __shfl_xor_sync(0xffffffffu, ssum, off);

        const float lse = m + logf(ssum);
        float* op = out + (size_t)g * DOUT;
#pragma unroll
        for (int j = 0; j < 8; ++j)
            op[lane + 32 * j] = z[j] - lse;
    }
}

// ---------------------------------------------------------------------------
extern "C" void kernel_launch(void* const* d_in, const int* in_sizes, int n_in,
                              void* d_out, int out_size)
{
    const float* enc  = nullptr;
    const float* Wm   = nullptr;
    const float* bias = nullptr;
    const int*   cls  = nullptr;
    const int*   ls   = nullptr;
    for (int i = 0; i < n_in; ++i) {
        switch (in_sizes[i]) {
            case 134217728: enc  = (const float*)d_in[i]; break;
            case 262144:    Wm   = (const float*)d_in[i]; break;
            case 256:       bias = (const float*)d_in[i]; break;
            case 2048:      cls  = (const int*)d_in[i];   break;
            case 32:        ls   = (const int*)d_in[i];   break;
            default: break;
        }
    }

    // 1) balanced segment reduce into (pre-zeroed) g_segsum: single wave
    dim3 g1(S / TILE_S, B);
    seg_tile_kernel<<<g1, 256>>>(enc, cls, ls);

    // 2) GEMM + bias*count + log_softmax; 80KB dynamic smem (one-shot A stage)
    const int smem_bytes = 1024 * 20 * (int)sizeof(float);   // 81920
    cudaFuncSetAttribute(gemm_lsm_kernel,
                         cudaFuncAttributeMaxDynamicSharedMemorySize, smem_bytes);
    gemm_lsm_kernel<<<(B * NSEG) / TILE_M, 512, smem_bytes>>>(
        Wm, bias, cls, ls, (float*)d_out);
}